// round 10
// baseline (speedup 1.0000x reference)
#include <cuda_runtime.h>
#include <cuda_bf16.h>
#include <cstdint>

#define L     768
#define CIN   384
#define CO    32
#define NO    128
#define EPS   1e-5f

// ---------------- device scratch (no allocations allowed) ----------------
__device__ float          g_right[L * CO];
__device__ __nv_bfloat16  g_lh   [L * CO];   // left hi
__device__ __nv_bfloat16  g_ll   [L * CO];   // left lo

// ---------------- PTX helpers (family-common, sm_80+) ----------------
__device__ __forceinline__ uint32_t smem_u32(const void* p) {
    uint32_t a;
    asm("{ .reg .u64 t; cvta.to.shared.u64 t, %1; cvt.u32.u64 %0, t; }"
        : "=r"(a) : "l"(p));
    return a;
}
__device__ __forceinline__ void ldsm_x4(uint32_t* r, uint32_t addr) {
    asm volatile("ldmatrix.sync.aligned.m8n8.x4.shared.b16 {%0,%1,%2,%3}, [%4];"
                 : "=r"(r[0]), "=r"(r[1]), "=r"(r[2]), "=r"(r[3]) : "r"(addr));
}
__device__ __forceinline__ void ldsm_x4t(uint32_t* r, uint32_t addr) {
    asm volatile("ldmatrix.sync.aligned.m8n8.x4.trans.shared.b16 {%0,%1,%2,%3}, [%4];"
                 : "=r"(r[0]), "=r"(r[1]), "=r"(r[2]), "=r"(r[3]) : "r"(addr));
}
__device__ __forceinline__ void mma16816(float* d, const uint32_t* a, const uint32_t* b) {
    asm volatile(
        "mma.sync.aligned.m16n8k16.row.col.f32.bf16.bf16.f32 "
        "{%0,%1,%2,%3}, {%4,%5,%6,%7}, {%8,%9}, {%0,%1,%2,%3};"
        : "+f"(d[0]), "+f"(d[1]), "+f"(d[2]), "+f"(d[3])
        : "r"(a[0]), "r"(a[1]), "r"(a[2]), "r"(a[3]), "r"(b[0]), "r"(b[1]));
}
__device__ __forceinline__ void cp16(uint32_t dst, const void* src) {
    asm volatile("cp.async.ca.shared.global [%0], [%1], 16;"
                 :: "r"(dst), "l"(src) : "memory");
}
#define CP_COMMIT() asm volatile("cp.async.commit_group;" ::: "memory")
#define CP_WAIT0()  asm volatile("cp.async.wait_group 0;" ::: "memory")

// ============================================================================
// Kernel A: per-row LayerNorm -> left/right projections -> lh/ll + right.
// (B2 and base are computed inside big_kernel from right + Wo.)
// ============================================================================
__global__ __launch_bounds__(256)
void prep_kernel(const float* __restrict__ act,  const float* __restrict__ mask,
                 const float* __restrict__ gamma, const float* __restrict__ beta,
                 const float* __restrict__ Wl,   const float* __restrict__ bl,
                 const float* __restrict__ Wr,   const float* __restrict__ br)
{
    __shared__ float sx[CIN];
    __shared__ float sred[512];
    __shared__ float sdot[256];

    const int j = blockIdx.x;
    const int t = threadIdx.x;
    const float* arow = act + j * CIN;

    float s = 0.f, s2 = 0.f;
    for (int c = t; c < CIN; c += 256) {
        float v = arow[c];
        sx[c] = v;
        s += v; s2 += v * v;
    }
    sred[t] = s; sred[256 + t] = s2;
    __syncthreads();
    for (int off = 128; off > 0; off >>= 1) {
        if (t < off) {
            sred[t]       += sred[t + off];
            sred[256 + t] += sred[256 + t + off];
        }
        __syncthreads();
    }
    const float mean = sred[0] * (1.f / CIN);
    const float var  = sred[256] * (1.f / CIN) - mean * mean;
    const float rstd = rsqrtf(var + EPS);

    for (int c = t; c < CIN; c += 256)
        sx[c] = (sx[c] - mean) * rstd * gamma[c] + beta[c];
    __syncthreads();

    // Projections: lr = t>>7, q = (t>>5)&3, c = t&31 (lane-consecutive c)
    {
        const int lr = t >> 7;
        const int q  = (t >> 5) & 3;
        const int c  = t & 31;
        const float* W = lr ? Wr : Wl;
        const int ci0  = q * (CIN / 4);
        float dot = 0.f;
        #pragma unroll 8
        for (int ci = ci0; ci < ci0 + CIN / 4; ci++)
            dot += sx[ci] * W[ci * CO + c];
        sdot[t] = dot;
    }
    __syncthreads();
    if (((t >> 5) & 3) == 0) {
        const int lr = t >> 7;
        const int c  = t & 31;
        const float bias = lr ? br[c] : bl[c];
        const float val  = mask[j] *
            (sdot[t] + sdot[t + 32] + sdot[t + 64] + sdot[t + 96] + bias);
        if (lr == 0) {
            __nv_bfloat16 h = __float2bfloat16_rn(val);
            g_lh[j * CO + c] = h;
            g_ll[j * CO + c] = __float2bfloat16_rn(val - __bfloat162float(h));
        } else {
            g_right[j * CO + c] = val;
        }
    }
}

// ============================================================================
// Kernel B: block = (i, 64-row j-tile). 256 threads, 4 CTAs/SM (reg diet).
//   sB = B2_i (bf16 hi/lo) computed in-kernel from right[i] + Wo;
//   base = bo - right@Wd computed in-kernel.
//   D = A(64xK96) @ B2(K96x128), acc init = base -> epilogue pure STG.64.
// Warps: 2 m-strips(32) x 4 n-strips(32); warp = 2 m-tiles x 4 n-tiles.
// ============================================================================
#define SA_STRIDE 72
#define SB_STRIDE 136

__global__ __launch_bounds__(256, 4)
void big_kernel(const float* __restrict__ Wo, const float* __restrict__ bo,
                float* __restrict__ out)
{
    __shared__ __nv_bfloat16 sA[64 * SA_STRIDE];   // 9216 B
    __shared__ __nv_bfloat16 sB[64 * SB_STRIDE];   // 17408 B
    __shared__ float sBase[NO];

    const int t  = threadIdx.x;
    const int i  = blockIdx.x;
    const int jt = blockIdx.y * 64;                // grid.y = 12 -> full 768

    const uint32_t saBase = smem_u32(sA);

    // ---- stage sA via cp.async (64 rows x {lh,ll} x 4 chunks = 512 cp16) ----
    #pragma unroll
    for (int it = 0; it < 2; it++) {
        const int idx = t + it * 256;
        const int j  = idx >> 3;
        const int s  = (idx >> 2) & 1;
        const int ch = idx & 3;
        const void* src = s ? (const void*)(g_ll + (jt + j) * CO + ch * 8)
                            : (const void*)(g_lh + (jt + j) * CO + ch * 8);
        cp16(saBase + (j * SA_STRIDE + s * 32 + ch * 8) * 2, src);
    }
    CP_COMMIT();

    // ---- compute sB: B2[c][d] = right[i,c]*Wp[c,d] + Wd[c,d], hi/lo ----
    {
        const float* rrow = g_right + i * CO;
        #pragma unroll
        for (int it = 0; it < 8; it++) {
            const int idx = t + it * 256;       // 32 c x 64 d-pairs
            const int c  = idx >> 6;
            const int dp = idx & 63;
            const float  r  = __ldg(&rrow[c]);
            const float2 wp = *(const float2*)&Wo[c * NO + 2 * dp];
            const float2 wd = *(const float2*)&Wo[(CO + c) * NO + 2 * dp];
            const float v0 = fmaf(r, wp.x, wd.x);
            const float v1 = fmaf(r, wp.y, wd.y);
            const __nv_bfloat16 h0 = __float2bfloat16_rn(v0);
            const __nv_bfloat16 h1 = __float2bfloat16_rn(v1);
            const __nv_bfloat16 l0 = __float2bfloat16_rn(v0 - __bfloat162float(h0));
            const __nv_bfloat16 l1 = __float2bfloat16_rn(v1 - __bfloat162float(h1));
            const uint32_t hp = ((uint32_t)__bfloat16_as_ushort(h1) << 16)
                              |  (uint32_t)__bfloat16_as_ushort(h0);
            const uint32_t lp = ((uint32_t)__bfloat16_as_ushort(l1) << 16)
                              |  (uint32_t)__bfloat16_as_ushort(l0);
            *(uint32_t*)((char*)sB + (c * SB_STRIDE + 2 * dp) * 2)        = hp;
            *(uint32_t*)((char*)sB + ((32 + c) * SB_STRIDE + 2 * dp) * 2) = lp;
        }
    }

    // ---- compute sBase: bo[d] - sum_c right[i,c]*Wd[c,d] ----
    if (t < 128) {
        const int d = t;
        const float* rrow = g_right + i * CO;
        float bm = 0.f;
        #pragma unroll 8
        for (int c = 0; c < CO; c++)
            bm += __ldg(&rrow[c]) * Wo[(CO + c) * NO + d];
        sBase[d] = bo[d] - bm;
    }

    CP_WAIT0();
    __syncthreads();

    const int lane = t & 31;
    const int wid  = t >> 5;
    const int mOff = (wid & 1) * 32;
    const int nOff = (wid >> 1) * 32;

    const uint32_t aAddr0 = saBase + ((mOff + (lane & 15)) * SA_STRIDE + (lane >> 4) * 8) * 2;
    const uint32_t bAddr0 = smem_u32(sB) +
        ((lane & 15) * SB_STRIDE + nOff + (lane >> 4) * 8) * 2;

    float acc[2][4][4];
    #pragma unroll
    for (int nt = 0; nt < 4; nt++) {
        const float2 bb = *(const float2*)&sBase[nOff + nt * 8 + (lane & 3) * 2];
        #pragma unroll
        for (int mt = 0; mt < 2; mt++) {
            acc[mt][nt][0] = bb.x; acc[mt][nt][1] = bb.y;
            acc[mt][nt][2] = bb.x; acc[mt][nt][3] = bb.y;
        }
    }

    // logical k-steps: lh*bh (2), lh*bl (2), ll*bh (2)
    const int aK[6] = {0, 16, 0, 16, 32, 48};
    const int bK[6] = {0, 16, 32, 48, 0, 16};

    #pragma unroll
    for (int ks = 0; ks < 6; ks++) {
        uint32_t af[2][4], bf[2][4];
        ldsm_x4(af[0], aAddr0 + (uint32_t)(aK[ks] * 2));
        ldsm_x4(af[1], aAddr0 + (uint32_t)((16 * SA_STRIDE + aK[ks]) * 2));
        ldsm_x4t(bf[0], bAddr0 + (uint32_t)((bK[ks] * SB_STRIDE) * 2));
        ldsm_x4t(bf[1], bAddr0 + (uint32_t)((bK[ks] * SB_STRIDE + 16) * 2));
        #pragma unroll
        for (int mt = 0; mt < 2; mt++)
            #pragma unroll
            for (int nt = 0; nt < 4; nt++)
                mma16816(acc[mt][nt], af[mt], &bf[nt >> 1][(nt & 1) * 2]);
    }

    // ---- epilogue: direct STG.64 (sector-optimal), streaming hint ----
    const int dBase = nOff + (lane & 3) * 2;
    float* outI = out + ((size_t)i * L + jt) * NO;
    #pragma unroll
    for (int mt = 0; mt < 2; mt++) {
        const int r0 = mOff + mt * 16 + (lane >> 2);
        float* p0 = outI + (size_t)r0 * NO;
        float* p1 = p0 + 8 * NO;
        #pragma unroll
        for (int nt = 0; nt < 4; nt++) {
            const int d = dBase + nt * 8;
            __stcs((float2*)(p0 + d), make_float2(acc[mt][nt][0], acc[mt][nt][1]));
            __stcs((float2*)(p1 + d), make_float2(acc[mt][nt][2], acc[mt][nt][3]));
        }
    }
}

// ============================================================================
extern "C" void kernel_launch(void* const* d_in, const int* in_sizes, int n_in,
                              void* d_out, int out_size)
{
    (void)in_sizes; (void)n_in; (void)out_size;
    const float* act   = (const float*)d_in[0];
    const float* mask  = (const float*)d_in[1];
    const float* gamma = (const float*)d_in[2];
    const float* beta  = (const float*)d_in[3];
    const float* Wl    = (const float*)d_in[4];
    const float* bl    = (const float*)d_in[5];
    const float* Wr    = (const float*)d_in[6];
    const float* br    = (const float*)d_in[7];
    const float* Wo    = (const float*)d_in[8];
    const float* bo    = (const float*)d_in[9];
    float* out = (float*)d_out;

    prep_kernel<<<L, 256>>>(act, mask, gamma, beta, Wl, bl, Wr, br);

    dim3 grid(L, 12);   // 12 * 64 = 768 j rows (R9 bug: was 6)
    big_kernel<<<grid, 256>>>(Wo, bo, out);
}

// round 11
// speedup vs baseline: 1.0849x; 1.0849x over previous
#include <cuda_runtime.h>
#include <cuda_bf16.h>
#include <cstdint>

#define L     768
#define CIN   384
#define CO    32
#define NO    128
#define EPS   1e-5f

// ---------------- device scratch (no allocations allowed) ----------------
__device__ float          g_base [L * NO];               // bo[d] - (right@Wd)[i,d]
__device__ __nv_bfloat16  g_lh   [L * CO];               // left hi
__device__ __nv_bfloat16  g_ll   [L * CO];               // left lo
__device__ __nv_bfloat16  g_B2h  [(size_t)L * CO * NO];  // per-i B2 hi  [i][c][d]
__device__ __nv_bfloat16  g_B2l  [(size_t)L * CO * NO];  // per-i B2 lo

// ---------------- PTX helpers (family-common, sm_80+) ----------------
__device__ __forceinline__ uint32_t smem_u32(const void* p) {
    uint32_t a;
    asm("{ .reg .u64 t; cvta.to.shared.u64 t, %1; cvt.u32.u64 %0, t; }"
        : "=r"(a) : "l"(p));
    return a;
}
__device__ __forceinline__ void ldsm_x4(uint32_t* r, uint32_t addr) {
    asm volatile("ldmatrix.sync.aligned.m8n8.x4.shared.b16 {%0,%1,%2,%3}, [%4];"
                 : "=r"(r[0]), "=r"(r[1]), "=r"(r[2]), "=r"(r[3]) : "r"(addr));
}
__device__ __forceinline__ void ldsm_x4t(uint32_t* r, uint32_t addr) {
    asm volatile("ldmatrix.sync.aligned.m8n8.x4.trans.shared.b16 {%0,%1,%2,%3}, [%4];"
                 : "=r"(r[0]), "=r"(r[1]), "=r"(r[2]), "=r"(r[3]) : "r"(addr));
}
__device__ __forceinline__ void mma16816(float* d, const uint32_t* a, const uint32_t* b) {
    asm volatile(
        "mma.sync.aligned.m16n8k16.row.col.f32.bf16.bf16.f32 "
        "{%0,%1,%2,%3}, {%4,%5,%6,%7}, {%8,%9}, {%0,%1,%2,%3};"
        : "+f"(d[0]), "+f"(d[1]), "+f"(d[2]), "+f"(d[3])
        : "r"(a[0]), "r"(a[1]), "r"(a[2]), "r"(a[3]), "r"(b[0]), "r"(b[1]));
}
__device__ __forceinline__ void cp16(uint32_t dst, const void* src) {
    asm volatile("cp.async.ca.shared.global [%0], [%1], 16;"
                 :: "r"(dst), "l"(src) : "memory");
}
#define CP_COMMIT() asm volatile("cp.async.commit_group;" ::: "memory")
#define CP_WAIT0()  asm volatile("cp.async.wait_group 0;" ::: "memory")

// ============================================================================
// Kernel A (fused, R8-verified): LayerNorm -> projections ->
//   left bf16 hi/lo, base = bo - right@Wd, B2 = r*Wp + Wd (bf16 hi/lo).
// ============================================================================
__global__ __launch_bounds__(256)
void prep_kernel(const float* __restrict__ act,  const float* __restrict__ mask,
                 const float* __restrict__ gamma, const float* __restrict__ beta,
                 const float* __restrict__ Wl,   const float* __restrict__ bl,
                 const float* __restrict__ Wr,   const float* __restrict__ br,
                 const float* __restrict__ Wo,   const float* __restrict__ bo)
{
    __shared__ float sx[CIN];
    __shared__ float sred[512];
    __shared__ float sdot[256];
    __shared__ float slr[2 * CO];

    const int j = blockIdx.x;
    const int t = threadIdx.x;
    const float* arow = act + j * CIN;

    float s = 0.f, s2 = 0.f;
    for (int c = t; c < CIN; c += 256) {
        float v = arow[c];
        sx[c] = v;
        s += v; s2 += v * v;
    }
    sred[t] = s; sred[256 + t] = s2;
    __syncthreads();
    for (int off = 128; off > 0; off >>= 1) {
        if (t < off) {
            sred[t]       += sred[t + off];
            sred[256 + t] += sred[256 + t + off];
        }
        __syncthreads();
    }
    const float mean = sred[0] * (1.f / CIN);
    const float var  = sred[256] * (1.f / CIN) - mean * mean;
    const float rstd = rsqrtf(var + EPS);

    for (int c = t; c < CIN; c += 256)
        sx[c] = (sx[c] - mean) * rstd * gamma[c] + beta[c];
    __syncthreads();

    {
        const int lr = t >> 7;
        const int q  = (t >> 5) & 3;
        const int c  = t & 31;
        const float* W = lr ? Wr : Wl;
        const int ci0  = q * (CIN / 4);
        float dot = 0.f;
        #pragma unroll 8
        for (int ci = ci0; ci < ci0 + CIN / 4; ci++)
            dot += sx[ci] * W[ci * CO + c];
        sdot[t] = dot;
    }
    __syncthreads();
    if (((t >> 5) & 3) == 0) {
        const int lr = t >> 7;
        const int c  = t & 31;
        const float bias = lr ? br[c] : bl[c];
        const float val  = mask[j] *
            (sdot[t] + sdot[t + 32] + sdot[t + 64] + sdot[t + 96] + bias);
        slr[lr * CO + c] = val;
        if (lr == 0) {
            __nv_bfloat16 h = __float2bfloat16_rn(val);
            g_lh[j * CO + c] = h;
            g_ll[j * CO + c] = __float2bfloat16_rn(val - __bfloat162float(h));
        }
    }
    __syncthreads();

    if (t < 128) {
        const int d = t;
        float bm = 0.f;
        #pragma unroll
        for (int c = 0; c < CO; c++)
            bm += slr[CO + c] * Wo[(CO + c) * NO + d];
        g_base[j * NO + d] = bo[d] - bm;
    }

    {
        const int d  = t & 127;
        const int c0 = (t >> 7) * 16;
        __nv_bfloat16* bh  = g_B2h + ((size_t)j * CO) * NO + d;
        __nv_bfloat16* bl2 = g_B2l + ((size_t)j * CO) * NO + d;
        #pragma unroll 4
        for (int c = c0; c < c0 + 16; c++) {
            float v = slr[CO + c] * Wo[c * NO + d] + Wo[(CO + c) * NO + d];
            __nv_bfloat16 h = __float2bfloat16_rn(v);
            bh[c * NO]  = h;
            bl2[c * NO] = __float2bfloat16_rn(v - __bfloat162float(h));
        }
    }
}

// ============================================================================
// Kernel B: block = (i, third), 512 threads = 16 warps (4m x 4n strips of 32).
// 2 j-tiles of 128, cp.async double-buffered sA; B2/base precomputed.
// Per-warp tile 32x32 -> acc 32 regs; forced <=64 regs -> 2 CTAs = 32 warps/SM.
// ============================================================================
#define SA_STRIDE 72
#define SB_STRIDE 136
#define SA_BYTES  (128 * SA_STRIDE * 2)    // 18432
#define SB_OFF    (2 * SA_BYTES)           // 36864
#define SMEM_TOTAL (SB_OFF + 64 * SB_STRIDE * 2)   // 54272

__global__ __launch_bounds__(512, 2)
void big_kernel(float* __restrict__ out)
{
    extern __shared__ char smem[];
    const uint32_t smemBase = smem_u32(smem);

    const int t     = threadIdx.x;
    const int i     = blockIdx.x;
    const int third = blockIdx.y;
    const int lane  = t & 31;
    const int wid   = t >> 5;
    const int mOff  = (wid & 3) * 32;
    const int nOff  = (wid >> 2) * 32;

    // ---- prologue: prefetch tile 0 sA (1024 cp16 over 512 threads) ----
    {
        const int jt = third * 256;
        #pragma unroll
        for (int it = 0; it < 2; it++) {
            const int idx = t + it * 512;
            const int j  = idx >> 3;
            const int s  = (idx >> 2) & 1;
            const int ch = idx & 3;
            const void* src = s ? (const void*)(g_ll + (jt + j) * CO + ch * 8)
                                : (const void*)(g_lh + (jt + j) * CO + ch * 8);
            cp16(smemBase + (j * SA_STRIDE + s * 32 + ch * 8) * 2, src);
        }
        CP_COMMIT();
    }

    // ---- stage sB (once per block; B2 L2-resident) ----
    {
        const uint4* srcH = (const uint4*)(g_B2h + (size_t)i * CO * NO);
        const uint4* srcL = (const uint4*)(g_B2l + (size_t)i * CO * NO);
        #pragma unroll
        for (int it = 0; it < 2; it++) {
            const int idx = t + it * 512;
            const int r  = idx >> 4;
            const int ch = idx & 15;
            const uint4 v = (r < 32) ? srcH[r * 16 + ch] : srcL[(r - 32) * 16 + ch];
            *(uint4*)(smem + SB_OFF + (r * SB_STRIDE + ch * 8) * 2) = v;
        }
    }

    // ---- base in registers (constant across tiles) ----
    float2 baseR[4];
    {
        const float* bp = g_base + i * NO + nOff + (lane & 3) * 2;
        #pragma unroll
        for (int nt = 0; nt < 4; nt++)
            baseR[nt] = *(const float2*)(bp + nt * 8);
    }

    const uint32_t bAddr0 = smemBase + SB_OFF +
        ((lane & 15) * SB_STRIDE + nOff + (lane >> 4) * 8) * 2;
    const uint32_t aLaneOff = ((mOff + (lane & 15)) * SA_STRIDE + (lane >> 4) * 8) * 2;

    // logical k-steps: lh*bh (2), lh*bl (2), ll*bh (2)
    const int aK[6] = {0, 16, 0, 16, 32, 48};
    const int bK[6] = {0, 16, 32, 48, 0, 16};

    #pragma unroll 1
    for (int tt = 0; tt < 2; tt++) {
        CP_WAIT0();
        __syncthreads();

        if (tt < 1) {
            const int jt = (third * 2 + tt + 1) * 128;
            const uint32_t dstB = smemBase + SA_BYTES;
            #pragma unroll
            for (int it = 0; it < 2; it++) {
                const int idx = t + it * 512;
                const int j  = idx >> 3;
                const int s  = (idx >> 2) & 1;
                const int ch = idx & 3;
                const void* src = s ? (const void*)(g_ll + (jt + j) * CO + ch * 8)
                                    : (const void*)(g_lh + (jt + j) * CO + ch * 8);
                cp16(dstB + (j * SA_STRIDE + s * 32 + ch * 8) * 2, src);
            }
            CP_COMMIT();
        }

        const uint32_t aAddr0 = smemBase + (tt & 1) * SA_BYTES + aLaneOff;

        float acc[2][4][4];
        #pragma unroll
        for (int nt = 0; nt < 4; nt++) {
            #pragma unroll
            for (int mt = 0; mt < 2; mt++) {
                acc[mt][nt][0] = baseR[nt].x; acc[mt][nt][1] = baseR[nt].y;
                acc[mt][nt][2] = baseR[nt].x; acc[mt][nt][3] = baseR[nt].y;
            }
        }

        #pragma unroll
        for (int ks = 0; ks < 6; ks++) {
            uint32_t af[2][4], bf[2][4];
            ldsm_x4(af[0], aAddr0 + (uint32_t)(aK[ks] * 2));
            ldsm_x4(af[1], aAddr0 + (uint32_t)((16 * SA_STRIDE + aK[ks]) * 2));
            ldsm_x4t(bf[0], bAddr0 + (uint32_t)((bK[ks] * SB_STRIDE) * 2));
            ldsm_x4t(bf[1], bAddr0 + (uint32_t)((bK[ks] * SB_STRIDE + 16) * 2));
            #pragma unroll
            for (int mt = 0; mt < 2; mt++)
                #pragma unroll
                for (int nt = 0; nt < 4; nt++)
                    mma16816(acc[mt][nt], af[mt], &bf[nt >> 1][(nt & 1) * 2]);
        }

        // ---- epilogue: direct STG.64, streaming hint ----
        const int jt = (third * 2 + tt) * 128;
        const int dBase = nOff + (lane & 3) * 2;
        float* outI = out + ((size_t)i * L + jt) * NO;
        #pragma unroll
        for (int mt = 0; mt < 2; mt++) {
            const int r0 = mOff + mt * 16 + (lane >> 2);
            float* p0 = outI + (size_t)r0 * NO;
            float* p1 = p0 + 8 * NO;
            #pragma unroll
            for (int nt = 0; nt < 4; nt++) {
                const int d = dBase + nt * 8;
                __stcs((float2*)(p0 + d), make_float2(acc[mt][nt][0], acc[mt][nt][1]));
                __stcs((float2*)(p1 + d), make_float2(acc[mt][nt][2], acc[mt][nt][3]));
            }
        }
    }
}

// ============================================================================
extern "C" void kernel_launch(void* const* d_in, const int* in_sizes, int n_in,
                              void* d_out, int out_size)
{
    (void)in_sizes; (void)n_in; (void)out_size;
    const float* act   = (const float*)d_in[0];
    const float* mask  = (const float*)d_in[1];
    const float* gamma = (const float*)d_in[2];
    const float* beta  = (const float*)d_in[3];
    const float* Wl    = (const float*)d_in[4];
    const float* bl    = (const float*)d_in[5];
    const float* Wr    = (const float*)d_in[6];
    const float* br    = (const float*)d_in[7];
    const float* Wo    = (const float*)d_in[8];
    const float* bo    = (const float*)d_in[9];
    float* out = (float*)d_out;

    static bool attr_set = false;
    if (!attr_set) {
        cudaFuncSetAttribute(big_kernel,
                             cudaFuncAttributeMaxDynamicSharedMemorySize, SMEM_TOTAL);
        attr_set = true;
    }

    prep_kernel<<<L, 256>>>(act, mask, gamma, beta, Wl, bl, Wr, br, Wo, bo);

    dim3 grid(L, 3);
    big_kernel<<<grid, 512, SMEM_TOTAL>>>(out);
}

// round 12
// speedup vs baseline: 1.3776x; 1.2698x over previous
#include <cuda_runtime.h>
#include <cuda_bf16.h>
#include <cstdint>

#define L     768
#define CIN   384
#define CO    32
#define NO    128
#define EPS   1e-5f

// ---------------- device scratch (no allocations allowed) ----------------
__device__ float          g_base [L * NO];               // bo[d] - (right@Wd)[i,d]
__device__ __nv_bfloat16  g_lh   [L * CO];               // left hi
__device__ __nv_bfloat16  g_ll   [L * CO];               // left lo
__device__ __nv_bfloat16  g_B2h  [(size_t)L * CO * NO];  // per-i B2 hi  [i][c][d]
__device__ __nv_bfloat16  g_B2l  [(size_t)L * CO * NO];  // per-i B2 lo

// ---------------- PTX helpers (family-common, sm_80+) ----------------
__device__ __forceinline__ uint32_t smem_u32(const void* p) {
    uint32_t a;
    asm("{ .reg .u64 t; cvta.to.shared.u64 t, %1; cvt.u32.u64 %0, t; }"
        : "=r"(a) : "l"(p));
    return a;
}
__device__ __forceinline__ void ldsm_x4(uint32_t* r, uint32_t addr) {
    asm volatile("ldmatrix.sync.aligned.m8n8.x4.shared.b16 {%0,%1,%2,%3}, [%4];"
                 : "=r"(r[0]), "=r"(r[1]), "=r"(r[2]), "=r"(r[3]) : "r"(addr));
}
__device__ __forceinline__ void ldsm_x4t(uint32_t* r, uint32_t addr) {
    asm volatile("ldmatrix.sync.aligned.m8n8.x4.trans.shared.b16 {%0,%1,%2,%3}, [%4];"
                 : "=r"(r[0]), "=r"(r[1]), "=r"(r[2]), "=r"(r[3]) : "r"(addr));
}
__device__ __forceinline__ void mma16816(float* d, const uint32_t* a, const uint32_t* b) {
    asm volatile(
        "mma.sync.aligned.m16n8k16.row.col.f32.bf16.bf16.f32 "
        "{%0,%1,%2,%3}, {%4,%5,%6,%7}, {%8,%9}, {%0,%1,%2,%3};"
        : "+f"(d[0]), "+f"(d[1]), "+f"(d[2]), "+f"(d[3])
        : "r"(a[0]), "r"(a[1]), "r"(a[2]), "r"(a[3]), "r"(b[0]), "r"(b[1]));
}
__device__ __forceinline__ void cp16(uint32_t dst, const void* src) {
    asm volatile("cp.async.ca.shared.global [%0], [%1], 16;"
                 :: "r"(dst), "l"(src) : "memory");
}
#define CP_COMMIT() asm volatile("cp.async.commit_group;" ::: "memory")
#define CP_WAIT0()  asm volatile("cp.async.wait_group 0;" ::: "memory")

// ============================================================================
// Kernel A (fused, R8-verified): LayerNorm -> projections ->
//   left bf16 hi/lo, base = bo - right@Wd, B2 = r*Wp + Wd (bf16 hi/lo).
// ============================================================================
__global__ __launch_bounds__(256)
void prep_kernel(const float* __restrict__ act,  const float* __restrict__ mask,
                 const float* __restrict__ gamma, const float* __restrict__ beta,
                 const float* __restrict__ Wl,   const float* __restrict__ bl,
                 const float* __restrict__ Wr,   const float* __restrict__ br,
                 const float* __restrict__ Wo,   const float* __restrict__ bo)
{
    __shared__ float sx[CIN];
    __shared__ float sred[512];
    __shared__ float sdot[256];
    __shared__ float slr[2 * CO];

    const int j = blockIdx.x;
    const int t = threadIdx.x;
    const float* arow = act + j * CIN;

    float s = 0.f, s2 = 0.f;
    for (int c = t; c < CIN; c += 256) {
        float v = arow[c];
        sx[c] = v;
        s += v; s2 += v * v;
    }
    sred[t] = s; sred[256 + t] = s2;
    __syncthreads();
    for (int off = 128; off > 0; off >>= 1) {
        if (t < off) {
            sred[t]       += sred[t + off];
            sred[256 + t] += sred[256 + t + off];
        }
        __syncthreads();
    }
    const float mean = sred[0] * (1.f / CIN);
    const float var  = sred[256] * (1.f / CIN) - mean * mean;
    const float rstd = rsqrtf(var + EPS);

    for (int c = t; c < CIN; c += 256)
        sx[c] = (sx[c] - mean) * rstd * gamma[c] + beta[c];
    __syncthreads();

    {
        const int lr = t >> 7;
        const int q  = (t >> 5) & 3;
        const int c  = t & 31;
        const float* W = lr ? Wr : Wl;
        const int ci0  = q * (CIN / 4);
        float dot = 0.f;
        #pragma unroll 8
        for (int ci = ci0; ci < ci0 + CIN / 4; ci++)
            dot += sx[ci] * W[ci * CO + c];
        sdot[t] = dot;
    }
    __syncthreads();
    if (((t >> 5) & 3) == 0) {
        const int lr = t >> 7;
        const int c  = t & 31;
        const float bias = lr ? br[c] : bl[c];
        const float val  = mask[j] *
            (sdot[t] + sdot[t + 32] + sdot[t + 64] + sdot[t + 96] + bias);
        slr[lr * CO + c] = val;
        if (lr == 0) {
            __nv_bfloat16 h = __float2bfloat16_rn(val);
            g_lh[j * CO + c] = h;
            g_ll[j * CO + c] = __float2bfloat16_rn(val - __bfloat162float(h));
        }
    }
    __syncthreads();

    if (t < 128) {
        const int d = t;
        float bm = 0.f;
        #pragma unroll
        for (int c = 0; c < CO; c++)
            bm += slr[CO + c] * Wo[(CO + c) * NO + d];
        g_base[j * NO + d] = bo[d] - bm;
    }

    {
        const int d  = t & 127;
        const int c0 = (t >> 7) * 16;
        __nv_bfloat16* bh  = g_B2h + ((size_t)j * CO) * NO + d;
        __nv_bfloat16* bl2 = g_B2l + ((size_t)j * CO) * NO + d;
        #pragma unroll 4
        for (int c = c0; c < c0 + 16; c++) {
            float v = slr[CO + c] * Wo[c * NO + d] + Wo[(CO + c) * NO + d];
            __nv_bfloat16 h = __float2bfloat16_rn(v);
            bh[c * NO]  = h;
            bl2[c * NO] = __float2bfloat16_rn(v - __bfloat162float(h));
        }
    }
}

// ============================================================================
// Kernel B (R8 structure): block = (i, third), 256 thr, 2 j-tiles of 128,
// cp.async double-buffered sA, B-fragment reuse.
// NEW: per-warp sync-free staged epilogue -> fully coalesced STG.128.
// ============================================================================
#define SA_STRIDE 72
#define SB_STRIDE 136
#define SA_BYTES  (128 * SA_STRIDE * 2)            // 18432
#define SB_OFF    (2 * SA_BYTES)                   // 36864
#define ST_OFF    (SB_OFF + 64 * SB_STRIDE * 2)    // 54272
#define ST_STRIDE 72                               // floats; conflict-free both phases
#define ST_WARP_BYTES (16 * ST_STRIDE * 4)         // 4608 per warp
#define SMEM_TOTAL (ST_OFF + 8 * ST_WARP_BYTES)    // 91136

__global__ __launch_bounds__(256, 2)
void big_kernel(float* __restrict__ out)
{
    extern __shared__ char smem[];
    const uint32_t smemBase = smem_u32(smem);

    const int t     = threadIdx.x;
    const int i     = blockIdx.x;
    const int third = blockIdx.y;
    const int lane  = t & 31;
    const int wid   = t >> 5;
    const int mOff  = (wid & 3) * 32;
    const int nOff  = (wid >> 2) * 64;

    float* sW = (float*)(smem + ST_OFF) + wid * (16 * ST_STRIDE);

    // ---- prologue: prefetch tile 0 sA via cp.async ----
    {
        const int jt = third * 256;
        #pragma unroll
        for (int idx = t; idx < 1024; idx += 256) {
            const int j  = idx >> 3;
            const int s  = (idx >> 2) & 1;
            const int ch = idx & 3;
            const void* src = s ? (const void*)(g_ll + (jt + j) * CO + ch * 8)
                                : (const void*)(g_lh + (jt + j) * CO + ch * 8);
            cp16(smemBase + (j * SA_STRIDE + s * 32 + ch * 8) * 2, src);
        }
        CP_COMMIT();
    }

    // ---- stage sB (once per block; B2 L2-resident) ----
    {
        const uint4* srcH = (const uint4*)(g_B2h + (size_t)i * CO * NO);
        const uint4* srcL = (const uint4*)(g_B2l + (size_t)i * CO * NO);
        #pragma unroll
        for (int idx = t; idx < 1024; idx += 256) {
            const int r  = idx >> 4;
            const int ch = idx & 15;
            const uint4 v = (r < 32) ? srcH[r * 16 + ch] : srcL[(r - 32) * 16 + ch];
            *(uint4*)(smem + SB_OFF + (r * SB_STRIDE + ch * 8) * 2) = v;
        }
    }

    // ---- base in registers (constant across tiles) ----
    float2 baseR[8];
    {
        const float* bp = g_base + i * NO + nOff + (lane & 3) * 2;
        #pragma unroll
        for (int nt = 0; nt < 8; nt++)
            baseR[nt] = *(const float2*)(bp + nt * 8);
    }

    const uint32_t bAddr0 = smemBase + SB_OFF +
        ((lane & 15) * SB_STRIDE + nOff + (lane >> 4) * 8) * 2;
    const uint32_t aLaneOff = ((mOff + (lane & 15)) * SA_STRIDE + (lane >> 4) * 8) * 2;

    #pragma unroll 1
    for (int tt = 0; tt < 2; tt++) {
        CP_WAIT0();
        __syncthreads();

        if (tt < 1) {
            const int jt = (third * 2 + tt + 1) * 128;
            const uint32_t dstB = smemBase + SA_BYTES;
            #pragma unroll
            for (int idx = t; idx < 1024; idx += 256) {
                const int j  = idx >> 3;
                const int s  = (idx >> 2) & 1;
                const int ch = idx & 3;
                const void* src = s ? (const void*)(g_ll + (jt + j) * CO + ch * 8)
                                    : (const void*)(g_lh + (jt + j) * CO + ch * 8);
                cp16(dstB + (j * SA_STRIDE + s * 32 + ch * 8) * 2, src);
            }
            CP_COMMIT();
        }

        const uint32_t aAddr0 = smemBase + (tt & 1) * SA_BYTES + aLaneOff;

        float acc[2][8][4];
        #pragma unroll
        for (int nt = 0; nt < 8; nt++) {
            #pragma unroll
            for (int mt = 0; mt < 2; mt++) {
                acc[mt][nt][0] = baseR[nt].x; acc[mt][nt][1] = baseR[nt].y;
                acc[mt][nt][2] = baseR[nt].x; acc[mt][nt][3] = baseR[nt].y;
            }
        }

        uint32_t afP[2][4], afT[2][4], bf[4][4];
        #define LOAD_A(dst, kk) { \
            ldsm_x4(dst[0], aAddr0 + (uint32_t)((kk) * 2)); \
            ldsm_x4(dst[1], aAddr0 + (uint32_t)((16 * SA_STRIDE + (kk)) * 2)); }
        #define LOAD_B(kk) { \
            _Pragma("unroll") \
            for (int q = 0; q < 4; q++) \
                ldsm_x4t(bf[q], bAddr0 + (uint32_t)(((kk) * SB_STRIDE + q * 16) * 2)); }
        #define MMA_ALL(af) { \
            _Pragma("unroll") \
            for (int mt = 0; mt < 2; mt++) \
                _Pragma("unroll") \
                for (int nt = 0; nt < 8; nt++) \
                    mma16816(acc[mt][nt], af[mt], &bf[nt >> 1][(nt & 1) * 2]); }

        LOAD_A(afP, 0);  LOAD_B(0);  MMA_ALL(afP);
        LOAD_A(afT, 32);             MMA_ALL(afT);
                         LOAD_B(32); MMA_ALL(afP);
        LOAD_A(afP, 16); LOAD_B(16); MMA_ALL(afP);
        LOAD_A(afT, 48);             MMA_ALL(afT);
                         LOAD_B(48); MMA_ALL(afP);

        #undef LOAD_A
        #undef LOAD_B
        #undef MMA_ALL

        // ---- epilogue: per-warp staged, sync-free, coalesced STG.128 ----
        const int jt = (third * 2 + tt) * 128;
        #pragma unroll
        for (int mt = 0; mt < 2; mt++) {
            // STS: scatter acc fragment into private 16x64 buffer (stride 72)
            {
                float* p0 = sW + (lane >> 2) * ST_STRIDE + (lane & 3) * 2;
                #pragma unroll
                for (int nt = 0; nt < 8; nt++) {
                    *(float2*)(p0 + nt * 8) =
                        make_float2(acc[mt][nt][0], acc[mt][nt][1]);
                    *(float2*)(p0 + 8 * ST_STRIDE + nt * 8) =
                        make_float2(acc[mt][nt][2], acc[mt][nt][3]);
                }
            }
            __syncwarp();
            // LDS row-linear + coalesced STG.128 (2 rows, 4 full lines / instr)
            {
                const int r0 = lane >> 4;           // 0/1
                const int c0 = (lane & 15) * 4;     // 0..60
                float* outBase = out + ((size_t)i * L + jt + mOff + mt * 16) * NO + nOff;
                #pragma unroll
                for (int q = 0; q < 8; q++) {
                    const int r = 2 * q + r0;
                    const float4 v = *(const float4*)(sW + r * ST_STRIDE + c0);
                    __stcs((float4*)(outBase + (size_t)r * NO + c0), v);
                }
            }
            __syncwarp();
        }
    }
}

// ============================================================================
extern "C" void kernel_launch(void* const* d_in, const int* in_sizes, int n_in,
                              void* d_out, int out_size)
{
    (void)in_sizes; (void)n_in; (void)out_size;
    const float* act   = (const float*)d_in[0];
    const float* mask  = (const float*)d_in[1];
    const float* gamma = (const float*)d_in[2];
    const float* beta  = (const float*)d_in[3];
    const float* Wl    = (const float*)d_in[4];
    const float* bl    = (const float*)d_in[5];
    const float* Wr    = (const float*)d_in[6];
    const float* br    = (const float*)d_in[7];
    const float* Wo    = (const float*)d_in[8];
    const float* bo    = (const float*)d_in[9];
    float* out = (float*)d_out;

    static bool attr_set = false;
    if (!attr_set) {
        cudaFuncSetAttribute(big_kernel,
                             cudaFuncAttributeMaxDynamicSharedMemorySize, SMEM_TOTAL);
        attr_set = true;
    }

    prep_kernel<<<L, 256>>>(act, mask, gamma, beta, Wl, bl, Wr, br, Wo, bo);

    dim3 grid(L, 3);
    big_kernel<<<grid, 256, SMEM_TOTAL>>>(out);
}